// round 3
// baseline (speedup 1.0000x reference)
#include <cuda_runtime.h>
#include <cstdint>

#define BB 32
#define LL 128
#define FF 128
#define RR 4096
#define HH (RR >> 1)
#define NN 262144
#define NGROUPS (BB * RR)      // 131072
#define CAP 32                 // Poisson(2) per group; P(count>32) ~ 1e-27

// Scratch (allocation-free: __device__ globals).
__device__ int    g_cnt[NGROUPS];
__device__ int    g_slots[NGROUPS * CAP];
__device__ float4 g_cw[NN];    // per-element fused coeffs (d0w0, d1w1, d2w2, d2w3)

// ---------------------------------------------------------------------------
// Kernel 1: zero the group counters (0.5 MB).
__global__ void dti_zero_kernel() {
    int i = blockIdx.x * blockDim.x + threadIdx.x;
    ((int4*)g_cnt)[i] = make_int4(0, 0, 0, 0);
}

// ---------------------------------------------------------------------------
// Kernel 2: one thread per element — fused coefficients + inverted index.
__global__ void dti_build_kernel(const float4* __restrict__ arg_w,  // (B*L) float4
                                 const float*  __restrict__ op_dist,
                                 const int* __restrict__ batch_idx,
                                 const int* __restrict__ slot_idx,
                                 const int* __restrict__ role_idx,
                                 int n) {
    int e = blockIdx.x * blockDim.x + threadIdx.x;
    if (e >= n) return;
    int b = __ldg(batch_idx + e);
    int s = __ldg(slot_idx + e);
    int j = __ldg(role_idx + e);
    float4 w = __ldg(arg_w + b * LL + s);
    float d0 = __ldg(op_dist + b * 3 + 0);
    float d1 = __ldg(op_dist + b * 3 + 1);
    float d2 = __ldg(op_dist + b * 3 + 2);
    g_cw[e] = make_float4(d0 * w.x, d1 * w.y, d2 * w.z, d2 * w.w);
    int key = (b << 12) + j;
    int pos = atomicAdd(&g_cnt[key], 1);
    if (pos < CAP) g_slots[key * CAP + pos] = e;
}

// ---------------------------------------------------------------------------
// Kernel 3: one warp per output row pair (r0=2k, r1=2k+1). Lane l owns
// features [4l, 4l+4). Pure gather: registers accumulate, single STG per row.
//
// Row r receives:
//   cons : group (r>>1), coeff (r even ? d2w2 : d2w3)   [all rows]
//   car  : group 2r,     coeff d0w0                     [r < H]
//   cdr  : group 2r+1,   coeff d1w1                     [1 <= r < H]
//   +d2*root_filler[b] at r == 1
__global__ void dti_gather_kernel(const float4* __restrict__ mem,
                                  const float4* __restrict__ root_filler,
                                  const float*  __restrict__ op_dist,
                                  float4* __restrict__ out) {
    int p = (blockIdx.x * blockDim.x + threadIdx.x) >> 5;   // pair id
    int lane = threadIdx.x & 31;
    int b = p >> 11;            // R/2 = 2048 pairs per batch
    int k = p & 2047;
    int gbase = b << 12;        // b * R

    float4 a0 = make_float4(0.f, 0.f, 0.f, 0.f);
    float4 a1 = make_float4(0.f, 0.f, 0.f, 0.f);

    // cons: group k feeds BOTH rows (read each element once).
    {
        int g = gbase + k;
        int cnt = min(__ldg(&g_cnt[g]), CAP);
        const int* sl = g_slots + g * CAP;
        for (int i = 0; i < cnt; i++) {
            int e = __ldg(sl + i);
            float4 c = __ldg(&g_cw[e]);
            float4 v = __ldg(mem + (size_t)e * (FF / 4) + lane);
            a0.x += c.z * v.x; a0.y += c.z * v.y; a0.z += c.z * v.z; a0.w += c.z * v.w;
            a1.x += c.w * v.x; a1.y += c.w * v.y; a1.z += c.w * v.z; a1.w += c.w * v.w;
        }
    }

    if (k < HH / 2) {   // rows 2k, 2k+1 < H: car + cdr contributions
        #pragma unroll
        for (int q = 0; q < 4; q++) {
            // q=0: car->r0 (group 4k,   comp x), q=1: cdr->r0 (group 4k+1, comp y)
            // q=2: car->r1 (group 4k+2, comp x), q=3: cdr->r1 (group 4k+3, comp y)
            if (q == 1 && k == 0) continue;   // cdr excludes group 1
            int g = gbase + 4 * k + q;
            int cnt = min(__ldg(&g_cnt[g]), CAP);
            const int* sl = g_slots + g * CAP;
            for (int i = 0; i < cnt; i++) {
                int e = __ldg(sl + i);
                float4 c = __ldg(&g_cw[e]);
                float co = (q & 1) ? c.y : c.x;
                float4 v = __ldg(mem + (size_t)e * (FF / 4) + lane);
                if (q < 2) {
                    a0.x += co * v.x; a0.y += co * v.y; a0.z += co * v.z; a0.w += co * v.w;
                } else {
                    a1.x += co * v.x; a1.y += co * v.y; a1.z += co * v.z; a1.w += co * v.w;
                }
            }
        }
    }

    if (k == 0) {   // row 1: += d2 * root_filler[b]
        float d2 = __ldg(op_dist + b * 3 + 2);
        float4 rf = __ldg(root_filler + b * (FF / 4) + lane);
        a1.x += d2 * rf.x; a1.y += d2 * rf.y; a1.z += d2 * rf.z; a1.w += d2 * rf.w;
    }

    // Each row written exactly once -> no init pass. Streaming stores.
    size_t o0 = ((size_t)(gbase + 2 * k)) * (FF / 4) + lane;
    __stcs(out + o0, a0);
    __stcs(out + o0 + (FF / 4), a1);
}

// ---------------------------------------------------------------------------
extern "C" void kernel_launch(void* const* d_in, const int* in_sizes, int n_in,
                              void* d_out, int out_size) {
    const float* mem = (const float*)d_in[0];
    const float* aw  = (const float*)d_in[1];
    const float* rf  = (const float*)d_in[2];
    const float* od  = (const float*)d_in[3];
    const int* bi    = (const int*)d_in[4];
    const int* si    = (const int*)d_in[5];
    const int* ri    = (const int*)d_in[6];
    float4* out      = (float4*)d_out;

    int n = in_sizes[4];  // N elements

    // 1. zero counters (int4 stores: NGROUPS/4 = 32768 threads)
    dti_zero_kernel<<<NGROUPS / 4 / 256, 256>>>();

    // 2. coefficients + inverted index
    dti_build_kernel<<<(n + 255) / 256, 256>>>((const float4*)aw, od, bi, si, ri, n);

    // 3. gather: B*R/2 = 65536 warps -> 8192 blocks x 256
    dti_gather_kernel<<<(BB * RR / 2) * 32 / 256, 256>>>(
        (const float4*)mem, (const float4*)rf, od, out);
}

// round 4
// speedup vs baseline: 1.2295x; 1.2295x over previous
#include <cuda_runtime.h>
#include <cstdint>

#define BB 32
#define LL 128
#define FF 128
#define RR 4096
#define HH (RR >> 1)
#define NN 262144
#define NGROUPS (BB * RR)      // 131072
#define CAP 32                 // Poisson(2) per group; overflow prob negligible, clamped anyway

// Scratch (allocation-free: __device__ globals).
__device__ int    g_cnt[NGROUPS];
__device__ int    g_slots[NGROUPS * CAP];
__device__ float4 g_cw[NN];    // per-element fused coeffs (d0w0, d1w1, d2w2, d2w3)

__device__ __forceinline__ void acc_fma(float4& a, float c, const float4& v) {
    a.x = fmaf(c, v.x, a.x); a.y = fmaf(c, v.y, a.y);
    a.z = fmaf(c, v.z, a.z); a.w = fmaf(c, v.w, a.w);
}

// ---------------------------------------------------------------------------
// Kernel 1: one thread per element — fused coefficients + inverted index.
__global__ void dti_build_kernel(const float4* __restrict__ arg_w,  // (B*L) float4
                                 const float*  __restrict__ op_dist,
                                 const int* __restrict__ batch_idx,
                                 const int* __restrict__ slot_idx,
                                 const int* __restrict__ role_idx,
                                 int n) {
    int e = blockIdx.x * blockDim.x + threadIdx.x;
    if (e >= n) return;
    int b = __ldg(batch_idx + e);
    int s = __ldg(slot_idx + e);
    int j = __ldg(role_idx + e);
    float4 w = __ldg(arg_w + b * LL + s);
    float d0 = __ldg(op_dist + b * 3 + 0);
    float d1 = __ldg(op_dist + b * 3 + 1);
    float d2 = __ldg(op_dist + b * 3 + 2);
    g_cw[e] = make_float4(d0 * w.x, d1 * w.y, d2 * w.z, d2 * w.w);
    int key = (b << 12) + j;
    int pos = atomicAdd(&g_cnt[key], 1);
    if (pos < CAP) g_slots[key * CAP + pos] = e;
}

// ---------------------------------------------------------------------------
// Strip-2 accumulate of one group's elements into one accumulator.
// sv = this lane's slot value (slot list was loaded warp-wide, 128B coalesced).
template <bool USE_Y>
__device__ __forceinline__ void group_acc(const float4* __restrict__ mem,
                                          int lane, int sv, int cnt, float4& a) {
    for (int i = 0; i < cnt; i += 2) {
        int e0 = __shfl_sync(0xffffffffu, sv, i);
        int e1 = __shfl_sync(0xffffffffu, sv, (i + 1) & 31);
        float4 c0 = __ldg(&g_cw[e0]);
        float4 v0 = __ldg(mem + (size_t)e0 * (FF / 4) + lane);
        bool h1 = (i + 1 < cnt);
        float4 c1, v1;
        if (h1) {
            c1 = __ldg(&g_cw[e1]);
            v1 = __ldg(mem + (size_t)e1 * (FF / 4) + lane);
        }
        acc_fma(a, USE_Y ? c0.y : c0.x, v0);
        if (h1) acc_fma(a, USE_Y ? c1.y : c1.x, v1);
    }
}

// ---------------------------------------------------------------------------
// Kernel 2: one warp per output row pair (r0=2k, r1=2k+1). Lane l owns
// features [4l, 4l+4). Pure gather; each output row written exactly once.
//
// Row r receives:
//   cons : group (r>>1), coeff (r even ? cw.z : cw.w)   [all rows]
//   car  : group 2r,     coeff cw.x                     [r < H]
//   cdr  : group 2r+1,   coeff cw.y                     [1 <= r < H]
//   +d2*root_filler[b] at r == 1
__global__ void dti_gather_kernel(const float4* __restrict__ mem,
                                  const float4* __restrict__ root_filler,
                                  const float*  __restrict__ op_dist,
                                  float4* __restrict__ out) {
    int p = (blockIdx.x * blockDim.x + threadIdx.x) >> 5;   // pair id
    int lane = threadIdx.x & 31;
    int b = p >> 11;            // R/2 = 2048 pairs per batch
    int k = p & 2047;
    int gbase = b << 12;        // b * R

    // ---- issue ALL index loads up front (independent, deep MLP) ----
    int g0 = gbase + k;
    int cnt0 = min(__ldg(&g_cnt[g0]), CAP);
    int sv0 = __ldg(&g_slots[g0 * CAP + lane]);         // 128B coalesced

    int cnt1 = 0, cnt2 = 0, cnt3 = 0, cnt4 = 0;
    int sv1 = 0, sv2 = 0, sv3 = 0, sv4 = 0;
    bool low = (k < HH / 2);
    if (low) {
        int4 c4 = __ldg((const int4*)&g_cnt[gbase + 4 * k]);
        cnt1 = min(c4.x, CAP);
        cnt2 = (k == 0) ? 0 : min(c4.y, CAP);           // cdr excludes role 1
        cnt3 = min(c4.z, CAP);
        cnt4 = min(c4.w, CAP);
        int sb = (gbase + 4 * k) * CAP;
        sv1 = __ldg(&g_slots[sb + lane]);
        sv2 = __ldg(&g_slots[sb + CAP + lane]);
        sv3 = __ldg(&g_slots[sb + 2 * CAP + lane]);
        sv4 = __ldg(&g_slots[sb + 3 * CAP + lane]);
    }

    float4 a0 = make_float4(0.f, 0.f, 0.f, 0.f);
    float4 a1 = make_float4(0.f, 0.f, 0.f, 0.f);

    // cons: group k feeds BOTH rows (each element's 512B read once for the pair)
    for (int i = 0; i < cnt0; i += 2) {
        int e0 = __shfl_sync(0xffffffffu, sv0, i);
        int e1 = __shfl_sync(0xffffffffu, sv0, (i + 1) & 31);
        float4 c0 = __ldg(&g_cw[e0]);
        float4 v0 = __ldg(mem + (size_t)e0 * (FF / 4) + lane);
        bool h1 = (i + 1 < cnt0);
        float4 c1, v1;
        if (h1) {
            c1 = __ldg(&g_cw[e1]);
            v1 = __ldg(mem + (size_t)e1 * (FF / 4) + lane);
        }
        acc_fma(a0, c0.z, v0); acc_fma(a1, c0.w, v0);
        if (h1) { acc_fma(a0, c1.z, v1); acc_fma(a1, c1.w, v1); }
    }

    if (low) {
        group_acc<false>(mem, lane, sv1, cnt1, a0);   // car  -> r0
        group_acc<true >(mem, lane, sv2, cnt2, a0);   // cdr  -> r0
        group_acc<false>(mem, lane, sv3, cnt3, a1);   // car  -> r1
        group_acc<true >(mem, lane, sv4, cnt4, a1);   // cdr  -> r1
    }

    if (k == 0) {   // row 1: += d2 * root_filler[b]
        float d2 = __ldg(op_dist + b * 3 + 2);
        float4 rf = __ldg(root_filler + b * (FF / 4) + lane);
        acc_fma(a1, d2, rf);
    }

    // One streaming store per row; output never read -> evict-first.
    size_t o0 = ((size_t)(gbase + 2 * k)) * (FF / 4) + lane;
    __stcs(out + o0, a0);
    __stcs(out + o0 + (FF / 4), a1);
}

// ---------------------------------------------------------------------------
extern "C" void kernel_launch(void* const* d_in, const int* in_sizes, int n_in,
                              void* d_out, int out_size) {
    const float* mem = (const float*)d_in[0];
    const float* aw  = (const float*)d_in[1];
    const float* rf  = (const float*)d_in[2];
    const float* od  = (const float*)d_in[3];
    const int* bi    = (const int*)d_in[4];
    const int* si    = (const int*)d_in[5];
    const int* ri    = (const int*)d_in[6];
    float4* out      = (float4*)d_out;

    int n = in_sizes[4];  // N elements

    // 1. zero counters via memset node (0.5 MB, near-peak BW)
    void* cnt_ptr = nullptr;
    cudaGetSymbolAddress(&cnt_ptr, g_cnt);
    cudaMemsetAsync(cnt_ptr, 0, NGROUPS * sizeof(int), 0);

    // 2. coefficients + inverted index
    dti_build_kernel<<<(n + 255) / 256, 256>>>((const float4*)aw, od, bi, si, ri, n);

    // 3. gather: B*R/2 = 65536 warps -> 8192 blocks x 256
    dti_gather_kernel<<<(BB * RR / 2) * 32 / 256, 256>>>(
        (const float4*)mem, (const float4*)rf, od, out);
}